// round 8
// baseline (speedup 1.0000x reference)
#include <cuda_runtime.h>
#include <math.h>

#define NNODES 10000
#define NHID   128
#define EMAX   160000

// ---------------- scratch (device globals; no allocation allowed) ----------
__device__ float g_X0 [NNODES * NHID];
__device__ float g_X1 [NNODES * NHID];
__device__ float g_AGG[NNODES * 512];    // per-head aggregated X (normalized)
__device__ float g_V  [NNODES * 1024];   // [conv(512) | res(512)]
__device__ float g_as [NNODES * 4];
__device__ float g_ad [NNODES * 4];
__device__ float g_fold[1024];           // [src folds 512 | dst folds 512]
__device__ int   g_deg[NNODES];
__device__ int   g_cur[NNODES];
__device__ int   g_off[NNODES + 1];
__device__ int   g_csr[EMAX];
__device__ int   g_is64;

// ---------------- helpers ---------------------------------------------------
__device__ __forceinline__ float lrelu(float x) { return x > 0.f ? x : 0.2f * x; }
__device__ __forceinline__ float eluf (float x) { return x > 0.f ? x : (__expf(x) - 1.f); }

__device__ __forceinline__ unsigned long long pk2(float lo, float hi) {
    unsigned long long r;
    asm("mov.b64 %0, {%1, %2};" : "=l"(r) : "f"(lo), "f"(hi));
    return r;
}
__device__ __forceinline__ void fma2(unsigned long long& d,
                                     unsigned long long a, unsigned long long b) {
    asm("fma.rn.f32x2 %0, %1, %2, %3;" : "=l"(d) : "l"(a), "l"(b), "l"(d));
}
__device__ __forceinline__ void upk2(float& lo, float& hi, unsigned long long v) {
    asm("mov.b64 {%0, %1}, %2;" : "=f"(lo), "=f"(hi) : "l"(v));
}

__device__ __forceinline__ int edge_at(const void* ei, int idx, int is64) {
    if (is64) return (int)((const long long*)ei)[idx];
    return ((const int*)ei)[idx];
}

// ---------------- init: zero deg/cur + dtype sniff + attention folds --------
// blocks 0..39: zero; block 0 also sniffs; blocks 40..43: fold vectors
__global__ void init_kernel(const void* ei,
                            const float* __restrict__ gat_w,
                            const float* __restrict__ att_src,
                            const float* __restrict__ att_dst)
{
    if (blockIdx.x >= 40) {
        int h = blockIdx.x - 40;         // head 0..3
        int t = threadIdx.x;
        int c = t & 127;
        const float* att = (t < 128) ? att_src : att_dst;
        int off = (t < 128) ? 0 : 512;
        float s = 0.f;
        for (int k = 0; k < 128; k++)
            s = fmaf(att[h * 128 + k], gat_w[(size_t)(h * 128 + k) * 128 + c], s);
        g_fold[off + h * 128 + c] = s;
        return;
    }
    int i = blockIdx.x * blockDim.x + threadIdx.x;
    if (i < NNODES) { g_deg[i] = 0; g_cur[i] = 0; }
    if (blockIdx.x == 0) {
        __shared__ int acc[256];
        int t = threadIdx.x;
        const unsigned* w = (const unsigned*)ei;
        unsigned o = 0;
        #pragma unroll
        for (int j = 0; j < 8; j++) o |= w[(t + j * 256) * 2 + 1];
        acc[t] = (int)(o != 0);
        __syncthreads();
        for (int s = 128; s > 0; s >>= 1) {
            if (t < s) acc[t] |= acc[t + s];
            __syncthreads();
        }
        if (t == 0) g_is64 = acc[0] ? 0 : 1;
    }
}

// ---------------- CSR build -------------------------------------------------
__global__ void count_kernel(const void* __restrict__ ei, int E) {
    int e = blockIdx.x * blockDim.x + threadIdx.x;
    if (e < E) atomicAdd(&g_deg[edge_at(ei, E + e, g_is64)], 1);
}

__global__ void scan_kernel(int n) {   // 1 block, 1024 threads, shuffle scan
    __shared__ int wsum[32];
    int t = threadIdx.x, lane = t & 31, w = t >> 5;
    const int chunk = 10;
    int base_i = t * chunk;
    int s = 0;
    #pragma unroll
    for (int i = 0; i < chunk; i++) {
        int idx = base_i + i;
        if (idx < n) s += g_deg[idx];
    }
    int v = s;
    #pragma unroll
    for (int o = 1; o < 32; o <<= 1) {
        int u = __shfl_up_sync(0xffffffffu, v, o);
        if (lane >= o) v += u;
    }
    if (lane == 31) wsum[w] = v;
    __syncthreads();
    if (w == 0) {
        int x = wsum[lane];
        #pragma unroll
        for (int o = 1; o < 32; o <<= 1) {
            int u = __shfl_up_sync(0xffffffffu, x, o);
            if (lane >= o) x += u;
        }
        wsum[lane] = x;
    }
    __syncthreads();
    int run = (w ? wsum[w - 1] : 0) + v - s;
    #pragma unroll
    for (int i = 0; i < chunk; i++) {
        int idx = base_i + i;
        if (idx < n) { g_off[idx] = run; run += g_deg[idx]; }
    }
    if (t == 1023) g_off[n] = run;
}

__global__ void scatter_kernel(const void* __restrict__ ei, int E) {
    int e = blockIdx.x * blockDim.x + threadIdx.x;
    if (e < E) {
        int is64 = g_is64;
        int d = edge_at(ei, E + e, is64);
        int p = g_off[d] + atomicAdd(&g_cur[d], 1);
        g_csr[p] = edge_at(ei, e, is64);
    }
}

// ---------------- GEMM core (device): C[m,n] = sum_k A[m,k]*B[n,k] ---------
// BM=128, BN=64, BK=16, 128 threads, 8x8 tile, f32x2 packed acc along M.
__device__ __forceinline__ void gemm_core(
    const float* __restrict__ A, int lda,
    const float* __restrict__ B,
    const float* __restrict__ bias,
    float* __restrict__ C, int ldc,
    int M, int N, int K, int relu, int bm, int bn)
{
    __shared__ float As[2][16][132];
    __shared__ float Bs[2][16][68];

    const int tid = threadIdx.x;
    const int tx = tid & 7, ty = tid >> 3;
    const int lr  = tid >> 2;
    const int lk4 = tid & 3;

    float4 pa[4], pb[2];
    const int nt = K >> 4;

    {
        #pragma unroll
        for (int p = 0; p < 4; p++) {
            int gm = bm + p * 32 + lr;
            pa[p] = (gm < M) ? *(const float4*)(A + (size_t)gm * lda + lk4 * 4)
                             : make_float4(0, 0, 0, 0);
        }
        #pragma unroll
        for (int p = 0; p < 2; p++) {
            int gn = bn + p * 32 + lr;
            pb[p] = (gn < N) ? *(const float4*)(B + (size_t)gn * K + lk4 * 4)
                             : make_float4(0, 0, 0, 0);
        }
        #pragma unroll
        for (int p = 0; p < 4; p++) {
            int r = p * 32 + lr;
            As[0][lk4 * 4 + 0][r] = pa[p].x; As[0][lk4 * 4 + 1][r] = pa[p].y;
            As[0][lk4 * 4 + 2][r] = pa[p].z; As[0][lk4 * 4 + 3][r] = pa[p].w;
        }
        #pragma unroll
        for (int p = 0; p < 2; p++) {
            int r = p * 32 + lr;
            Bs[0][lk4 * 4 + 0][r] = pb[p].x; Bs[0][lk4 * 4 + 1][r] = pb[p].y;
            Bs[0][lk4 * 4 + 2][r] = pb[p].z; Bs[0][lk4 * 4 + 3][r] = pb[p].w;
        }
    }
    __syncthreads();

    unsigned long long acc[4][8];
    const unsigned long long zz = pk2(0.f, 0.f);
    #pragma unroll
    for (int i = 0; i < 4; i++)
        #pragma unroll
        for (int j = 0; j < 8; j++) acc[i][j] = zz;

    for (int t = 0; t < nt; t++) {
        int cur = t & 1;
        if (t + 1 < nt) {
            int kt = (t + 1) << 4;
            #pragma unroll
            for (int p = 0; p < 4; p++) {
                int gm = bm + p * 32 + lr;
                pa[p] = (gm < M) ? *(const float4*)(A + (size_t)gm * lda + kt + lk4 * 4)
                                 : make_float4(0, 0, 0, 0);
            }
            #pragma unroll
            for (int p = 0; p < 2; p++) {
                int gn = bn + p * 32 + lr;
                pb[p] = (gn < N) ? *(const float4*)(B + (size_t)gn * K + kt + lk4 * 4)
                                 : make_float4(0, 0, 0, 0);
            }
        }
        #pragma unroll
        for (int k = 0; k < 16; k++) {
            ulonglong2 ap0 = *(const ulonglong2*)&As[cur][k][ty * 8];
            ulonglong2 ap1 = *(const ulonglong2*)&As[cur][k][ty * 8 + 4];
            float4 b0 = *(const float4*)&Bs[cur][k][tx * 8];
            float4 b1 = *(const float4*)&Bs[cur][k][tx * 8 + 4];
            unsigned long long ad[4] = {ap0.x, ap0.y, ap1.x, ap1.y};
            unsigned long long bd[8] = {
                pk2(b0.x, b0.x), pk2(b0.y, b0.y), pk2(b0.z, b0.z), pk2(b0.w, b0.w),
                pk2(b1.x, b1.x), pk2(b1.y, b1.y), pk2(b1.z, b1.z), pk2(b1.w, b1.w)
            };
            #pragma unroll
            for (int i = 0; i < 4; i++)
                #pragma unroll
                for (int j = 0; j < 8; j++)
                    fma2(acc[i][j], ad[i], bd[j]);
        }
        if (t + 1 < nt) {
            int nxt = cur ^ 1;
            #pragma unroll
            for (int p = 0; p < 4; p++) {
                int r = p * 32 + lr;
                As[nxt][lk4 * 4 + 0][r] = pa[p].x; As[nxt][lk4 * 4 + 1][r] = pa[p].y;
                As[nxt][lk4 * 4 + 2][r] = pa[p].z; As[nxt][lk4 * 4 + 3][r] = pa[p].w;
            }
            #pragma unroll
            for (int p = 0; p < 2; p++) {
                int r = p * 32 + lr;
                Bs[nxt][lk4 * 4 + 0][r] = pb[p].x; Bs[nxt][lk4 * 4 + 1][r] = pb[p].y;
                Bs[nxt][lk4 * 4 + 2][r] = pb[p].z; Bs[nxt][lk4 * 4 + 3][r] = pb[p].w;
            }
            __syncthreads();
        }
    }

    const int n0 = bn + tx * 8;
    bool vec = (n0 + 8 <= N);
    float4 bias0 = make_float4(0, 0, 0, 0), bias1 = make_float4(0, 0, 0, 0);
    if (bias && vec) {
        bias0 = *(const float4*)(bias + n0);
        bias1 = *(const float4*)(bias + n0 + 4);
    }
    #pragma unroll
    for (int i = 0; i < 4; i++) {
        float lo[8], hi[8];
        #pragma unroll
        for (int j = 0; j < 8; j++) upk2(lo[j], hi[j], acc[i][j]);
        #pragma unroll
        for (int p = 0; p < 2; p++) {
            int gm = bm + ty * 8 + i * 2 + p;
            if (gm >= M) continue;
            float* v = p ? hi : lo;
            if (vec) {
                float4 o0 = make_float4(v[0] + bias0.x, v[1] + bias0.y,
                                        v[2] + bias0.z, v[3] + bias0.w);
                float4 o1 = make_float4(v[4] + bias1.x, v[5] + bias1.y,
                                        v[6] + bias1.z, v[7] + bias1.w);
                if (relu) {
                    o0.x = fmaxf(o0.x, 0.f); o0.y = fmaxf(o0.y, 0.f);
                    o0.z = fmaxf(o0.z, 0.f); o0.w = fmaxf(o0.w, 0.f);
                    o1.x = fmaxf(o1.x, 0.f); o1.y = fmaxf(o1.y, 0.f);
                    o1.z = fmaxf(o1.z, 0.f); o1.w = fmaxf(o1.w, 0.f);
                }
                *(float4*)(C + (size_t)gm * ldc + n0)     = o0;
                *(float4*)(C + (size_t)gm * ldc + n0 + 4) = o1;
            } else {
                #pragma unroll
                for (int j = 0; j < 8; j++) {
                    int gn = n0 + j;
                    if (gn >= N) continue;
                    float val = v[j];
                    if (bias) val += bias[gn];
                    if (relu) val = fmaxf(val, 0.f);
                    C[(size_t)gm * ldc + gn] = val;
                }
            }
        }
    }
}

// ---------------- generic GEMM (enc / dec) ----------------------------------
__global__ __launch_bounds__(128)
void gemm_kernel(const float* __restrict__ Aext, int Asel,
                 const float* __restrict__ B,
                 const float* __restrict__ bias,
                 float* __restrict__ Cext, int Csel,
                 int M, int N, int K, int lda, int ldc, int relu)
{
    const float* A = (Asel == 1) ? g_X0 : (Asel == 2) ? g_X1 : Aext;
    float* C = (Csel == 1) ? g_X0 : (Csel == 2) ? g_X1 : Cext;
    gemm_core(A, lda, B, bias, C, ldc, M, N, K, relu,
              blockIdx.x * 128, blockIdx.y * 64);
}

// ---------------- layer GEMM: conv (4 heads) + res in one launch ------------
// grid (79, 8, 2): z=0 conv (head = y>>1), z=1 res
__global__ __launch_bounds__(128)
void layer_gemm_kernel(const float* __restrict__ gat_w,
                       const float* __restrict__ res_w,
                       const float* __restrict__ res_b,
                       int in_sel)
{
    int bm = blockIdx.x * 128;
    int y = blockIdx.y;
    if (blockIdx.z == 0) {
        int h = y >> 1;
        gemm_core(g_AGG + h * 128, 512,
                  gat_w + (size_t)h * 128 * 128, nullptr,
                  g_V + h * 128, 1024,
                  NNODES, 128, 128, 0, bm, (y & 1) * 64);
    } else {
        const float* Xc = (in_sel == 1) ? g_X0 : g_X1;
        gemm_core(Xc, 128, res_w, res_b,
                  g_V + 512, 1024,
                  NNODES, 512, 128, 0, bm, y * 64);
    }
}

// ---------------- attention logits: a_src/a_dst via folds -------------------
__global__ __launch_bounds__(128)
void logit_kernel(int in_sel)
{
    const float* X = (in_sel == 1) ? g_X0 : g_X1;
    int n = blockIdx.x;
    int lane = threadIdx.x & 31;
    int h = threadIdx.x >> 5;
    const float* xr = X + (size_t)n * 128;
    float s0 = 0.f, s1 = 0.f;
    #pragma unroll
    for (int j = 0; j < 4; j++) {
        float v = xr[lane + j * 32];
        s0 = fmaf(v, g_fold[h * 128 + lane + j * 32], s0);
        s1 = fmaf(v, g_fold[512 + h * 128 + lane + j * 32], s1);
    }
    #pragma unroll
    for (int o = 16; o > 0; o >>= 1) {
        s0 += __shfl_down_sync(0xffffffffu, s0, o);
        s1 += __shfl_down_sync(0xffffffffu, s1, o);
    }
    if (lane == 0) { g_as[n * 4 + h] = s0; g_ad[n * 4 + h] = s1; }
}

// ---------------- node aggregation over X (512B per edge) -------------------
// one block per destination node, 128 threads; thread t = channel c.
// agg[d, h*128+c] = (1/ssum_h) * ( X[d,c] + sum_e w_h(e) * X[src(e), c] )
__global__ __launch_bounds__(128)
void node_agg_kernel(int in_sel)
{
    const float* X = (in_sel == 1) ? g_X0 : g_X1;
    const int d = blockIdx.x, t = threadIdx.x;

    __shared__ float s_adv[4];
    __shared__ float s_ls [4];
    __shared__ float sw[128];    // 32 edges x 4 heads
    __shared__ int   si[32];

    if (t < 4) {
        float adv = g_ad[d * 4 + t];
        s_adv[t] = adv;
        s_ls[t]  = lrelu(g_as[d * 4 + t] + adv);
    }
    __syncthreads();

    const int e0 = g_off[d], e1 = g_off[d + 1];

    float xd = X[(size_t)d * 128 + t];
    float a0 = xd, a1 = xd, a2 = xd, a3 = xd;         // self, w = 1
    float s0 = 1.f, s1 = 1.f, s2 = 1.f, s3 = 1.f;

    const int jj = t >> 2, hh = t & 3;
    const float adv_h = s_adv[hh];
    const float ls_h  = s_ls[hh];

    for (int base = e0; base < e1; base += 32) {
        int cnt = min(32, e1 - base);
        if (jj < cnt) {
            int s = g_csr[base + jj];
            if (hh == 0) si[jj] = s;
            float as = g_as[s * 4 + hh];
            sw[jj * 4 + hh] = __expf(lrelu(as + adv_h) - ls_h);
        }
        __syncthreads();

        for (int j = 0; j < cnt; j++) {
            float4 w4 = *(const float4*)&sw[j * 4];
            float x = X[(size_t)si[j] * 128 + t];
            a0 = fmaf(w4.x, x, a0); s0 += w4.x;
            a1 = fmaf(w4.y, x, a1); s1 += w4.y;
            a2 = fmaf(w4.z, x, a2); s2 += w4.z;
            a3 = fmaf(w4.w, x, a3); s3 += w4.w;
        }
        __syncthreads();
    }

    float* out = g_AGG + (size_t)d * 512;
    out[t]       = a0 * (1.f / s0);
    out[128 + t] = a1 * (1.f / s1);
    out[256 + t] = a2 * (1.f / s2);
    out[384 + t] = a3 * (1.f / s3);
}

// ---------------- epilogue: z = mean_h elu(conv + gat_b + res) --------------
__global__ __launch_bounds__(256)
void epi_kernel(const float* __restrict__ gat_b, int out_sel)
{
    float* Xn = (out_sel == 1) ? g_X0 : g_X1;
    int idx = blockIdx.x * blockDim.x + threadIdx.x;   // 0 .. 10000*128-1
    if (idx >= NNODES * 128) return;
    int d = idx >> 7, t = idx & 127;
    const float* vd = g_V + (size_t)d * 1024;
    float4 cv = ((const float4*)vd)[t];
    float4 rs = ((const float4*)(vd + 512))[t];
    float4 gb = ((const float4*)gat_b)[t];
    float z = 0.25f * (eluf(cv.x + rs.x + gb.x) +
                       eluf(cv.y + rs.y + gb.y) +
                       eluf(cv.z + rs.z + gb.z) +
                       eluf(cv.w + rs.w + gb.w));
    Xn[(size_t)d * 128 + t] = z;
}

// ---------------- host ------------------------------------------------------
extern "C" void kernel_launch(void* const* d_in, const int* in_sizes, int n_in,
                              void* d_out, int out_size)
{
    const float* x       = (const float*)d_in[0];
    const void*  ei      = d_in[1];
    const float* enc_w   = (const float*)d_in[2];
    const float* enc_b   = (const float*)d_in[3];
    const float* res_w   = (const float*)d_in[4];
    const float* res_b   = (const float*)d_in[5];
    const float* gat_w   = (const float*)d_in[6];
    const float* att_src = (const float*)d_in[7];
    const float* att_dst = (const float*)d_in[8];
    const float* gat_b   = (const float*)d_in[9];
    const float* dec_w   = (const float*)d_in[10];
    const float* dec_b   = (const float*)d_in[11];
    int E = in_sizes[1] / 2;

    // init (zero + sniff + folds) and CSR
    init_kernel<<<44, 256>>>(ei, gat_w, att_src, att_dst);
    count_kernel<<<(E + 255) / 256, 256>>>(ei, E);
    scan_kernel<<<1, 1024>>>(NNODES);
    scatter_kernel<<<(E + 255) / 256, 256>>>(ei, E);

    // encoder: X0 = relu(x @ enc_w^T + enc_b)
    gemm_kernel<<<dim3(79, 2), 128>>>(x, 0, enc_w, enc_b, nullptr, 1,
                                      NNODES, 128, 256, 256, 128, 1);

    for (int layer = 0; layer < 2; layer++) {
        int in_sel  = (layer == 0) ? 1 : 2;
        int out_sel = (layer == 0) ? 2 : 1;
        logit_kernel<<<NNODES, 128>>>(in_sel);
        node_agg_kernel<<<NNODES, 128>>>(in_sel);
        layer_gemm_kernel<<<dim3(79, 8, 2), 128>>>(gat_w, res_w, res_b, in_sel);
        epi_kernel<<<(NNODES * 128 + 255) / 256, 256>>>(gat_b, out_sel);
    }

    // decoder: out = X0 @ dec_w^T + dec_b
    gemm_kernel<<<dim3(79, 1), 128>>>(nullptr, 1, dec_w, dec_b,
                                      (float*)d_out, 0,
                                      NNODES, 40, 128, 128, 40, 0);
}

// round 9
// speedup vs baseline: 1.0815x; 1.0815x over previous
#include <cuda_runtime.h>
#include <math.h>

#define NNODES 10000
#define NHID   128
#define UC     1032   // U row: xh(512) | res(512) | a_src(4) | a_dst(4)
#define NB     1032
#define EMAX   160000

// ---------------- scratch (device globals; no allocation allowed) ----------
__device__ float g_X0[NNODES * NHID];
__device__ float g_X1[NNODES * NHID];
__device__ float g_U [NNODES * UC];
__device__ float g_fold[8 * 128];   // rows: 0..3 fold(att_src) h, 4..7 fold(att_dst) h
__device__ int   g_deg[NNODES];     // zero-initialized at load; re-zeroed by node_L0
__device__ int   g_cur[NNODES];
__device__ int   g_off[NNODES + 1];
__device__ int   g_csr[EMAX];
__device__ int   g_is64;

// ---------------- helpers ---------------------------------------------------
__device__ __forceinline__ float lrelu(float x) { return x > 0.f ? x : 0.2f * x; }
__device__ __forceinline__ float eluf (float x) { return x > 0.f ? x : (__expf(x) - 1.f); }

__device__ __forceinline__ unsigned long long pk2(float lo, float hi) {
    unsigned long long r;
    asm("mov.b64 %0, {%1, %2};" : "=l"(r) : "f"(lo), "f"(hi));
    return r;
}
__device__ __forceinline__ void fma2(unsigned long long& d,
                                     unsigned long long a, unsigned long long b) {
    asm("fma.rn.f32x2 %0, %1, %2, %3;" : "=l"(d) : "l"(a), "l"(b), "l"(d));
}
__device__ __forceinline__ void upk2(float& lo, float& hi, unsigned long long v) {
    asm("mov.b64 {%0, %1}, %2;" : "=f"(lo), "=f"(hi) : "l"(v));
}

__device__ __forceinline__ int edge_at(const void* ei, int idx, int is64) {
    if (is64) return (int)((const long long*)ei)[idx];
    return ((const int*)ei)[idx];
}

// ---------------- init: fold rows (blocks 0..7) + dtype sniff (block 8) -----
__global__ __launch_bounds__(128)
void init_kernel(const void* ei,
                 const float* __restrict__ gat_w,
                 const float* __restrict__ att_src,
                 const float* __restrict__ att_dst)
{
    int b = blockIdx.x, t = threadIdx.x;
    if (b < 8) {
        int h = b & 3;
        const float* att = (b < 4) ? att_src : att_dst;
        float s = 0.f;
        for (int k = 0; k < 128; k++)
            s = fmaf(att[h * 128 + k], gat_w[(size_t)(h * 128 + k) * 128 + t], s);
        g_fold[b * 128 + t] = s;
    } else {
        __shared__ int acc[128];
        const unsigned* w = (const unsigned*)ei;
        unsigned o = 0;
        #pragma unroll
        for (int j = 0; j < 16; j++) o |= w[(t + j * 128) * 2 + 1];
        acc[t] = (int)(o != 0);
        __syncthreads();
        for (int s = 64; s > 0; s >>= 1) {
            if (t < s) acc[t] |= acc[t + s];
            __syncthreads();
        }
        if (t == 0) g_is64 = acc[0] ? 0 : 1;   // any nonzero odd word -> int32
    }
}

// ---------------- CSR build -------------------------------------------------
__global__ void count_kernel(const void* __restrict__ ei, int E) {
    int e = blockIdx.x * blockDim.x + threadIdx.x;
    if (e < E) atomicAdd(&g_deg[edge_at(ei, E + e, g_is64)], 1);
}

__global__ void scan_kernel(int n) {   // 1 block, 1024 threads, shuffle scan
    __shared__ int wsum[32];
    int t = threadIdx.x, lane = t & 31, w = t >> 5;
    const int chunk = 10;
    int base_i = t * chunk;
    int s = 0;
    #pragma unroll
    for (int i = 0; i < chunk; i++) {
        int idx = base_i + i;
        if (idx < n) s += g_deg[idx];
    }
    int v = s;
    #pragma unroll
    for (int o = 1; o < 32; o <<= 1) {
        int u = __shfl_up_sync(0xffffffffu, v, o);
        if (lane >= o) v += u;
    }
    if (lane == 31) wsum[w] = v;
    __syncthreads();
    if (w == 0) {
        int x = wsum[lane];
        #pragma unroll
        for (int o = 1; o < 32; o <<= 1) {
            int u = __shfl_up_sync(0xffffffffu, x, o);
            if (lane >= o) x += u;
        }
        wsum[lane] = x;
    }
    __syncthreads();
    int run = (w ? wsum[w - 1] : 0) + v - s;   // exclusive prefix
    #pragma unroll
    for (int i = 0; i < chunk; i++) {
        int idx = base_i + i;
        if (idx < n) { g_off[idx] = run; run += g_deg[idx]; }
    }
    if (t == 1023) g_off[n] = run;
}

__global__ void scatter_kernel(const void* __restrict__ ei, int E) {
    int e = blockIdx.x * blockDim.x + threadIdx.x;
    if (e < E) {
        int is64 = g_is64;
        int d = edge_at(ei, E + e, is64);
        int p = g_off[d] + atomicAdd(&g_cur[d], 1);
        g_csr[p] = edge_at(ei, e, is64);
    }
}

// ---------------- GEMM core -------------------------------------------------
// BM=128, BN=64, BK=16, 256 threads, double-buffered smem, f32x2 packed
// accumulators paired along M. LAYER mode: B rows resolved across
// gat_w(0..511) / res_w(512..1023) / g_fold(1024..1031); bias = res_b window.
template<bool LAYER>
__device__ __forceinline__ void gemm_core(
    const float* __restrict__ A, int lda,
    const float* __restrict__ B0, const float* __restrict__ B1,
    const float* __restrict__ bias,
    float* __restrict__ C, int ldc,
    int M, int N, int K, int relu, int bm, int bn)
{
    __shared__ float As[2][16][132];
    __shared__ float Bs[2][16][68];

    const int tid = threadIdx.x;
    const int tx = tid & 15, ty = tid >> 4;

    const int am0 = tid >> 2;
    const int am1 = 64 + (tid >> 2);
    const int ak4 = tid & 3;
    const int bn0 = tid >> 2;
    const int bk4 = tid & 3;

    // resolve B row pointer once
    const int gn_row = bn + bn0;
    const float* brow;
    if (LAYER) {
        if (gn_row < 512)       brow = B0 + (size_t)gn_row * 128;
        else if (gn_row < 1024) brow = B1 + (size_t)(gn_row - 512) * 128;
        else                    brow = g_fold + (size_t)(gn_row - 1024) * 128;
    } else {
        brow = B0 + (size_t)gn_row * K;
    }

    float4 pa0, pa1, pb;
    const int nt = K >> 4;

    {   // prologue (kt = 0)
        int gm0 = bm + am0, gm1 = bm + am1;
        pa0 = (gm0 < M) ? *(const float4*)(A + (size_t)gm0 * lda + ak4 * 4) : make_float4(0, 0, 0, 0);
        pa1 = (gm1 < M) ? *(const float4*)(A + (size_t)gm1 * lda + ak4 * 4) : make_float4(0, 0, 0, 0);
        pb  = (gn_row < N) ? *(const float4*)(brow + bk4 * 4) : make_float4(0, 0, 0, 0);
        As[0][ak4 * 4 + 0][am0] = pa0.x; As[0][ak4 * 4 + 1][am0] = pa0.y;
        As[0][ak4 * 4 + 2][am0] = pa0.z; As[0][ak4 * 4 + 3][am0] = pa0.w;
        As[0][ak4 * 4 + 0][am1] = pa1.x; As[0][ak4 * 4 + 1][am1] = pa1.y;
        As[0][ak4 * 4 + 2][am1] = pa1.z; As[0][ak4 * 4 + 3][am1] = pa1.w;
        Bs[0][bk4 * 4 + 0][bn0] = pb.x;  Bs[0][bk4 * 4 + 1][bn0] = pb.y;
        Bs[0][bk4 * 4 + 2][bn0] = pb.z;  Bs[0][bk4 * 4 + 3][bn0] = pb.w;
    }
    __syncthreads();

    unsigned long long acc[4][4];
    const unsigned long long zz = pk2(0.f, 0.f);
    #pragma unroll
    for (int i = 0; i < 4; i++)
        #pragma unroll
        for (int j = 0; j < 4; j++) acc[i][j] = zz;

    for (int t = 0; t < nt; t++) {
        int cur = t & 1;
        if (t + 1 < nt) {
            int kt = (t + 1) << 4;
            int gm0 = bm + am0, gm1 = bm + am1;
            pa0 = (gm0 < M) ? *(const float4*)(A + (size_t)gm0 * lda + kt + ak4 * 4) : make_float4(0, 0, 0, 0);
            pa1 = (gm1 < M) ? *(const float4*)(A + (size_t)gm1 * lda + kt + ak4 * 4) : make_float4(0, 0, 0, 0);
            pb  = (gn_row < N) ? *(const float4*)(brow + kt + bk4 * 4) : make_float4(0, 0, 0, 0);
        }
        #pragma unroll
        for (int k = 0; k < 16; k++) {
            ulonglong2 ap0 = *(const ulonglong2*)&As[cur][k][ty * 8];
            ulonglong2 ap1 = *(const ulonglong2*)&As[cur][k][ty * 8 + 4];
            float4 bv = *(const float4*)&Bs[cur][k][tx * 4];
            unsigned long long ad[4] = {ap0.x, ap0.y, ap1.x, ap1.y};
            unsigned long long bd[4] = {pk2(bv.x, bv.x), pk2(bv.y, bv.y),
                                        pk2(bv.z, bv.z), pk2(bv.w, bv.w)};
            #pragma unroll
            for (int i = 0; i < 4; i++) {
                fma2(acc[i][0], ad[i], bd[0]);
                fma2(acc[i][1], ad[i], bd[1]);
                fma2(acc[i][2], ad[i], bd[2]);
                fma2(acc[i][3], ad[i], bd[3]);
            }
        }
        if (t + 1 < nt) {
            int nxt = cur ^ 1;
            As[nxt][ak4 * 4 + 0][am0] = pa0.x; As[nxt][ak4 * 4 + 1][am0] = pa0.y;
            As[nxt][ak4 * 4 + 2][am0] = pa0.z; As[nxt][ak4 * 4 + 3][am0] = pa0.w;
            As[nxt][ak4 * 4 + 0][am1] = pa1.x; As[nxt][ak4 * 4 + 1][am1] = pa1.y;
            As[nxt][ak4 * 4 + 2][am1] = pa1.z; As[nxt][ak4 * 4 + 3][am1] = pa1.w;
            Bs[nxt][bk4 * 4 + 0][bn0] = pb.x;  Bs[nxt][bk4 * 4 + 1][bn0] = pb.y;
            Bs[nxt][bk4 * 4 + 2][bn0] = pb.z;  Bs[nxt][bk4 * 4 + 3][bn0] = pb.w;
            __syncthreads();
        }
    }

    #pragma unroll
    for (int i2 = 0; i2 < 4; i2++) {
        #pragma unroll
        for (int p = 0; p < 2; p++) {
            int gm = bm + ty * 8 + i2 * 2 + p;
            if (gm >= M) continue;
            #pragma unroll
            for (int j = 0; j < 4; j++) {
                float lo, hi;
                upk2(lo, hi, acc[i2][j]);
                float v = p ? hi : lo;
                int gn = bn + tx * 4 + j;
                if (gn >= N) continue;
                if (LAYER) {
                    if (gn >= 512 && gn < 1024) v += bias[gn - 512];
                } else if (bias) {
                    v += bias[gn];
                }
                if (relu) v = fmaxf(v, 0.f);
                C[(size_t)gm * ldc + gn] = v;
            }
        }
    }
}

// ---------------- generic GEMM (enc / dec) ----------------------------------
__global__ __launch_bounds__(256)
void gemm_generic(const float* __restrict__ Aext, int Asel,
                  const float* __restrict__ B,
                  const float* __restrict__ bias,
                  float* __restrict__ Cext, int Csel,
                  int M, int N, int K, int lda, int ldc, int relu)
{
    const float* A = (Asel == 1) ? g_X0 : (Asel == 2) ? g_X1 : Aext;
    float* C = (Csel == 1) ? g_X0 : (Csel == 2) ? g_X1 : Cext;
    gemm_core<false>(A, lda, B, nullptr, bias, C, ldc, M, N, K, relu,
                     blockIdx.x * 128, blockIdx.y * 64);
}

// ---------------- layer GEMM: U = Xc @ [gat_w; res_w; folds]^T + bias -------
__global__ __launch_bounds__(256)
void gemm_layer(const float* __restrict__ gat_w,
                const float* __restrict__ res_w,
                const float* __restrict__ res_b,
                int in_sel)
{
    const float* A = (in_sel == 1) ? g_X0 : g_X1;
    gemm_core<true>(A, 128, gat_w, res_w, res_b, g_U, UC,
                    NNODES, NB, 128, 0, blockIdx.x * 128, blockIdx.y * 64);
}

// ---------------- GAT aggregation + fused GraphCON epilogue ----------------
// one block per destination node, 128 threads; thread t owns flat channels
// 4t..4t+3 (head h = t>>5). Softmax stabilized by the SELF logit; per-edge
// weights computed ONCE into smem; aggregate loop unrolled x4.
__global__ __launch_bounds__(128)
void node_kernel(const float* __restrict__ gat_b, int out_sel, int zero_dc)
{
    float* Xnew = (out_sel == 1) ? g_X0 : g_X1;
    const int d = blockIdx.x, t = threadIdx.x;
    const int h = t >> 5;

    __shared__ float s_adv[4];
    __shared__ float s_ls [4];
    __shared__ float sw[128];    // 32 edges x 4 heads
    __shared__ int   si[32];

    const float* ud = g_U + (size_t)d * UC;
    if (t < 4) {
        float adv = ud[1028 + t];
        s_adv[t] = adv;
        s_ls[t]  = lrelu(ud[1024 + t] + adv);
    }
    if (zero_dc && t == 0) { g_deg[d] = 0; g_cur[d] = 0; }   // reset for next call
    __syncthreads();

    const int e0 = g_off[d], e1 = g_off[d + 1];

    float ssum = 1.f;                         // self weight = 1
    float4 acc = ((const float4*)ud)[t];

    const int jj = t >> 2, hh = t & 3;
    const float adv_h = s_adv[hh];
    const float ls_h  = s_ls[hh];

    for (int base = e0; base < e1; base += 32) {
        int cnt = min(32, e1 - base);
        if (jj < cnt) {
            int s = g_csr[base + jj];
            if (hh == 0) si[jj] = s;
            float as = g_U[(size_t)s * UC + 1024 + hh];
            sw[jj * 4 + hh] = __expf(lrelu(as + adv_h) - ls_h);
        }
        __syncthreads();

        int j = 0;
        for (; j + 4 <= cnt; j += 4) {
            int s0 = si[j], s1 = si[j + 1], s2 = si[j + 2], s3 = si[j + 3];
            float w0 = sw[j * 4 + h],      w1 = sw[j * 4 + 4 + h];
            float w2 = sw[j * 4 + 8 + h],  w3 = sw[j * 4 + 12 + h];
            float4 v0 = ((const float4*)(g_U + (size_t)s0 * UC))[t];
            float4 v1 = ((const float4*)(g_U + (size_t)s1 * UC))[t];
            float4 v2 = ((const float4*)(g_U + (size_t)s2 * UC))[t];
            float4 v3 = ((const float4*)(g_U + (size_t)s3 * UC))[t];
            acc.x = fmaf(w0, v0.x, acc.x); acc.y = fmaf(w0, v0.y, acc.y);
            acc.z = fmaf(w0, v0.z, acc.z); acc.w = fmaf(w0, v0.w, acc.w);
            acc.x = fmaf(w1, v1.x, acc.x); acc.y = fmaf(w1, v1.y, acc.y);
            acc.z = fmaf(w1, v1.z, acc.z); acc.w = fmaf(w1, v1.w, acc.w);
            acc.x = fmaf(w2, v2.x, acc.x); acc.y = fmaf(w2, v2.y, acc.y);
            acc.z = fmaf(w2, v2.z, acc.z); acc.w = fmaf(w2, v2.w, acc.w);
            acc.x = fmaf(w3, v3.x, acc.x); acc.y = fmaf(w3, v3.y, acc.y);
            acc.z = fmaf(w3, v3.z, acc.z); acc.w = fmaf(w3, v3.w, acc.w);
            ssum += (w0 + w1) + (w2 + w3);
        }
        for (; j < cnt; j++) {
            int s0 = si[j];
            float w0 = sw[j * 4 + h];
            float4 v0 = ((const float4*)(g_U + (size_t)s0 * UC))[t];
            acc.x = fmaf(w0, v0.x, acc.x); acc.y = fmaf(w0, v0.y, acc.y);
            acc.z = fmaf(w0, v0.z, acc.z); acc.w = fmaf(w0, v0.w, acc.w);
            ssum += w0;
        }
        __syncthreads();
    }

    float rcp = 1.f / ssum;
    float4 gb = ((const float4*)gat_b)[t];
    float4 rs = ((const float4*)(ud + 512))[t];
    float z = 0.25f * (eluf(fmaf(acc.x, rcp, gb.x + rs.x)) +
                       eluf(fmaf(acc.y, rcp, gb.y + rs.y)) +
                       eluf(fmaf(acc.z, rcp, gb.z + rs.z)) +
                       eluf(fmaf(acc.w, rcp, gb.w + rs.w)));
    Xnew[(size_t)d * NHID + t] = z;
}

// ---------------- host ------------------------------------------------------
extern "C" void kernel_launch(void* const* d_in, const int* in_sizes, int n_in,
                              void* d_out, int out_size)
{
    const float* x       = (const float*)d_in[0];
    const void*  ei      = d_in[1];
    const float* enc_w   = (const float*)d_in[2];
    const float* enc_b   = (const float*)d_in[3];
    const float* res_w   = (const float*)d_in[4];
    const float* res_b   = (const float*)d_in[5];
    const float* gat_w   = (const float*)d_in[6];
    const float* att_src = (const float*)d_in[7];
    const float* att_dst = (const float*)d_in[8];
    const float* gat_b   = (const float*)d_in[9];
    const float* dec_w   = (const float*)d_in[10];
    const float* dec_b   = (const float*)d_in[11];
    int E = in_sizes[1] / 2;

    // side stream + events for capture-fork (created per call; call count is
    // tiny — correctness + capture only; replays don't re-enter this function)
    cudaStream_t s2;
    cudaStreamCreateWithFlags(&s2, cudaStreamNonBlocking);
    cudaEvent_t evA, evB;
    cudaEventCreateWithFlags(&evA, cudaEventDisableTiming);
    cudaEventCreateWithFlags(&evB, cudaEventDisableTiming);

    // folds + dtype sniff (needed by both branches)
    init_kernel<<<9, 128>>>(ei, gat_w, att_src, att_dst);

    // fork: CSR build on side stream, concurrent with encoder + layer-0 GEMM
    cudaEventRecord(evA, 0);
    cudaStreamWaitEvent(s2, evA, 0);
    count_kernel<<<(E + 255) / 256, 256, 0, s2>>>(ei, E);
    scan_kernel<<<1, 1024, 0, s2>>>(NNODES);
    scatter_kernel<<<(E + 255) / 256, 256, 0, s2>>>(ei, E);
    cudaEventRecord(evB, s2);

    // main branch: encoder + layer-0 projections
    gemm_generic<<<dim3(79, 2), 256>>>(x, 0, enc_w, enc_b, nullptr, 1,
                                       NNODES, 128, 256, 256, 128, 1);
    gemm_layer<<<dim3(79, 17), 256>>>(gat_w, res_w, res_b, 1);

    // join: node needs CSR + U
    cudaStreamWaitEvent(0, evB, 0);
    node_kernel<<<NNODES, 128>>>(gat_b, 2, 1);   // layer 0, also re-zeroes deg/cur

    gemm_layer<<<dim3(79, 17), 256>>>(gat_w, res_w, res_b, 2);
    node_kernel<<<NNODES, 128>>>(gat_b, 1, 0);   // layer 1

    // decoder: out = X0 @ dec_w^T + dec_b
    gemm_generic<<<dim3(79, 1), 256>>>(nullptr, 1, dec_w, dec_b,
                                       (float*)d_out, 0,
                                       NNODES, 40, 128, 128, 40, 0);
}

// round 11
// speedup vs baseline: 1.3675x; 1.2645x over previous
#include <cuda_runtime.h>
#include <cuda_bf16.h>
#include <math.h>
#include <stdint.h>

#define NNODES 10000
#define NPAD   10112     // 79*128
#define NHID   128
#define UC     1032      // U row: xh(512) | res(512) | a_src(4) | a_dst(4)
#define NBPAD  1088      // 17*64
#define EMAX   160000

// ---------------- scratch (device globals; no allocation allowed) ----------
__device__ float g_X0[NNODES * NHID];
__device__ float g_X1[NNODES * NHID];
__device__ float g_U [NNODES * UC];
__device__ float g_fold[8 * 128];
__device__ __nv_bfloat16 g_Xhi[NPAD * 128];
__device__ __nv_bfloat16 g_Xlo[NPAD * 128];
__device__ __nv_bfloat16 g_Whi[NBPAD * 128];
__device__ __nv_bfloat16 g_Wlo[NBPAD * 128];
__device__ int   g_deg[NNODES];
__device__ int   g_cur[NNODES];
__device__ int   g_off[NNODES + 1];
__device__ int   g_csr[EMAX];
__device__ int   g_is64;

// ---------------- helpers ---------------------------------------------------
__device__ __forceinline__ float lrelu(float x) { return x > 0.f ? x : 0.2f * x; }
__device__ __forceinline__ float eluf (float x) { return x > 0.f ? x : (__expf(x) - 1.f); }

__device__ __forceinline__ unsigned long long pk2(float lo, float hi) {
    unsigned long long r;
    asm("mov.b64 %0, {%1, %2};" : "=l"(r) : "f"(lo), "f"(hi));
    return r;
}
__device__ __forceinline__ void fma2(unsigned long long& d,
                                     unsigned long long a, unsigned long long b) {
    asm("fma.rn.f32x2 %0, %1, %2, %3;" : "=l"(d) : "l"(a), "l"(b), "l"(d));
}
__device__ __forceinline__ void upk2(float& lo, float& hi, unsigned long long v) {
    asm("mov.b64 {%0, %1}, %2;" : "=f"(lo), "=f"(hi) : "l"(v));
}

__device__ __forceinline__ int edge_at(const void* ei, int idx, int is64) {
    if (is64) return (int)((const long long*)ei)[idx];
    return ((const int*)ei)[idx];
}

__device__ __forceinline__ uint32_t smem_u32(const void* p) {
    uint32_t a;
    asm("{ .reg .u64 t; cvta.to.shared.u64 t, %1; cvt.u32.u64 %0, t; }"
        : "=r"(a) : "l"(p));
    return a;
}

#define LDSM_X4(r, addr)                                                        \
    asm volatile("ldmatrix.sync.aligned.m8n8.x4.shared.b16 {%0,%1,%2,%3}, [%4];" \
        : "=r"((r)[0]), "=r"((r)[1]), "=r"((r)[2]), "=r"((r)[3]) : "r"(addr))

#define MMA_BF16(c, a, b0_, b1_)                                                \
    asm volatile("mma.sync.aligned.m16n8k16.row.col.f32.bf16.bf16.f32 "         \
        "{%0,%1,%2,%3}, {%4,%5,%6,%7}, {%8,%9}, {%0,%1,%2,%3};"                 \
        : "+f"((c)[0]), "+f"((c)[1]), "+f"((c)[2]), "+f"((c)[3])                \
        : "r"((a)[0]), "r"((a)[1]), "r"((a)[2]), "r"((a)[3]), "r"(b0_), "r"(b1_))

// ---------------- init: fold rows (blocks 0..7) + dtype sniff (block 8) -----
__global__ __launch_bounds__(128)
void init_kernel(const void* ei,
                 const float* __restrict__ gat_w,
                 const float* __restrict__ att_src,
                 const float* __restrict__ att_dst)
{
    int b = blockIdx.x, t = threadIdx.x;
    if (b < 8) {
        int h = b & 3;
        const float* att = (b < 4) ? att_src : att_dst;
        float s = 0.f;
        for (int k = 0; k < 128; k++)
            s = fmaf(att[h * 128 + k], gat_w[(size_t)(h * 128 + k) * 128 + t], s);
        g_fold[b * 128 + t] = s;
    } else {
        __shared__ int acc[128];
        const unsigned* w = (const unsigned*)ei;
        unsigned o = 0;
        #pragma unroll
        for (int j = 0; j < 16; j++) o |= w[(t + j * 128) * 2 + 1];
        acc[t] = (int)(o != 0);
        __syncthreads();
        for (int s = 64; s > 0; s >>= 1) {
            if (t < s) acc[t] |= acc[t + s];
            __syncthreads();
        }
        if (t == 0) g_is64 = acc[0] ? 0 : 1;
    }
}

// ---------------- weight / activation bf16-split conversion -----------------
__global__ __launch_bounds__(128)
void conv_w_kernel(const float* __restrict__ gat_w,
                   const float* __restrict__ res_w)
{
    int r = blockIdx.x, t = threadIdx.x;
    float v = 0.f;
    if (r < 512)       v = gat_w[(size_t)r * 128 + t];
    else if (r < 1024) v = res_w[(size_t)(r - 512) * 128 + t];
    else if (r < 1032) v = g_fold[(r - 1024) * 128 + t];
    __nv_bfloat16 hi = __float2bfloat16(v);
    float lo = v - __bfloat162float(hi);
    g_Whi[(size_t)r * 128 + t] = hi;
    g_Wlo[(size_t)r * 128 + t] = __float2bfloat16(lo);
}

__global__ __launch_bounds__(256)
void conv_x_kernel(int in_sel)
{
    const float* X = (in_sel == 1) ? g_X0 : g_X1;
    int idx = blockIdx.x * 256 + threadIdx.x;   // < NPAD*128
    float v = (idx < NNODES * 128) ? X[idx] : 0.f;
    __nv_bfloat16 hi = __float2bfloat16(v);
    float lo = v - __bfloat162float(hi);
    g_Xhi[idx] = hi;
    g_Xlo[idx] = __float2bfloat16(lo);
}

// ---------------- CSR build -------------------------------------------------
__global__ void count_kernel(const void* __restrict__ ei, int E) {
    int e = blockIdx.x * blockDim.x + threadIdx.x;
    if (e < E) atomicAdd(&g_deg[edge_at(ei, E + e, g_is64)], 1);
}

__global__ void scan_kernel(int n) {
    __shared__ int wsum[32];
    int t = threadIdx.x, lane = t & 31, w = t >> 5;
    const int chunk = 10;
    int base_i = t * chunk;
    int s = 0;
    #pragma unroll
    for (int i = 0; i < chunk; i++) {
        int idx = base_i + i;
        if (idx < n) s += g_deg[idx];
    }
    int v = s;
    #pragma unroll
    for (int o = 1; o < 32; o <<= 1) {
        int u = __shfl_up_sync(0xffffffffu, v, o);
        if (lane >= o) v += u;
    }
    if (lane == 31) wsum[w] = v;
    __syncthreads();
    if (w == 0) {
        int x = wsum[lane];
        #pragma unroll
        for (int o = 1; o < 32; o <<= 1) {
            int u = __shfl_up_sync(0xffffffffu, x, o);
            if (lane >= o) x += u;
        }
        wsum[lane] = x;
    }
    __syncthreads();
    int run = (w ? wsum[w - 1] : 0) + v - s;
    #pragma unroll
    for (int i = 0; i < chunk; i++) {
        int idx = base_i + i;
        if (idx < n) { g_off[idx] = run; run += g_deg[idx]; }
    }
    if (t == 1023) g_off[n] = run;
}

__global__ void scatter_kernel(const void* __restrict__ ei, int E) {
    int e = blockIdx.x * blockDim.x + threadIdx.x;
    if (e < E) {
        int is64 = g_is64;
        int d = edge_at(ei, E + e, is64);
        int p = g_off[d] + atomicAdd(&g_cur[d], 1);
        g_csr[p] = edge_at(ei, e, is64);
    }
}

// ---------------- SIMT GEMM core (enc / dec) --------------------------------
__device__ __forceinline__ void gemm_core(
    const float* __restrict__ A, int lda,
    const float* __restrict__ B,
    const float* __restrict__ bias,
    float* __restrict__ C, int ldc,
    int M, int N, int K, int relu, int bm, int bn)
{
    __shared__ float As[2][16][132];
    __shared__ float Bs[2][16][68];

    const int tid = threadIdx.x;
    const int tx = tid & 15, ty = tid >> 4;
    const int am0 = tid >> 2, am1 = 64 + (tid >> 2), ak4 = tid & 3;
    const int bn0 = tid >> 2, bk4 = tid & 3;

    const int gn_row = bn + bn0;
    const float* brow = B + (size_t)gn_row * K;

    float4 pa0, pa1, pb;
    const int nt = K >> 4;

    {
        int gm0 = bm + am0, gm1 = bm + am1;
        pa0 = (gm0 < M) ? *(const float4*)(A + (size_t)gm0 * lda + ak4 * 4) : make_float4(0, 0, 0, 0);
        pa1 = (gm1 < M) ? *(const float4*)(A + (size_t)gm1 * lda + ak4 * 4) : make_float4(0, 0, 0, 0);
        pb  = (gn_row < N) ? *(const float4*)(brow + bk4 * 4) : make_float4(0, 0, 0, 0);
        As[0][ak4 * 4 + 0][am0] = pa0.x; As[0][ak4 * 4 + 1][am0] = pa0.y;
        As[0][ak4 * 4 + 2][am0] = pa0.z; As[0][ak4 * 4 + 3][am0] = pa0.w;
        As[0][ak4 * 4 + 0][am1] = pa1.x; As[0][ak4 * 4 + 1][am1] = pa1.y;
        As[0][ak4 * 4 + 2][am1] = pa1.z; As[0][ak4 * 4 + 3][am1] = pa1.w;
        Bs[0][bk4 * 4 + 0][bn0] = pb.x;  Bs[0][bk4 * 4 + 1][bn0] = pb.y;
        Bs[0][bk4 * 4 + 2][bn0] = pb.z;  Bs[0][bk4 * 4 + 3][bn0] = pb.w;
    }
    __syncthreads();

    unsigned long long acc[4][4];
    const unsigned long long zz = pk2(0.f, 0.f);
    #pragma unroll
    for (int i = 0; i < 4; i++)
        #pragma unroll
        for (int j = 0; j < 4; j++) acc[i][j] = zz;

    for (int t = 0; t < nt; t++) {
        int cur = t & 1;
        if (t + 1 < nt) {
            int kt = (t + 1) << 4;
            int gm0 = bm + am0, gm1 = bm + am1;
            pa0 = (gm0 < M) ? *(const float4*)(A + (size_t)gm0 * lda + kt + ak4 * 4) : make_float4(0, 0, 0, 0);
            pa1 = (gm1 < M) ? *(const float4*)(A + (size_t)gm1 * lda + kt + ak4 * 4) : make_float4(0, 0, 0, 0);
            pb  = (gn_row < N) ? *(const float4*)(brow + kt + bk4 * 4) : make_float4(0, 0, 0, 0);
        }
        #pragma unroll
        for (int k = 0; k < 16; k++) {
            ulonglong2 ap0 = *(const ulonglong2*)&As[cur][k][ty * 8];
            ulonglong2 ap1 = *(const ulonglong2*)&As[cur][k][ty * 8 + 4];
            float4 bv = *(const float4*)&Bs[cur][k][tx * 4];
            unsigned long long ad[4] = {ap0.x, ap0.y, ap1.x, ap1.y};
            unsigned long long bd[4] = {pk2(bv.x, bv.x), pk2(bv.y, bv.y),
                                        pk2(bv.z, bv.z), pk2(bv.w, bv.w)};
            #pragma unroll
            for (int i = 0; i < 4; i++) {
                fma2(acc[i][0], ad[i], bd[0]);
                fma2(acc[i][1], ad[i], bd[1]);
                fma2(acc[i][2], ad[i], bd[2]);
                fma2(acc[i][3], ad[i], bd[3]);
            }
        }
        if (t + 1 < nt) {
            int nxt = cur ^ 1;
            As[nxt][ak4 * 4 + 0][am0] = pa0.x; As[nxt][ak4 * 4 + 1][am0] = pa0.y;
            As[nxt][ak4 * 4 + 2][am0] = pa0.z; As[nxt][ak4 * 4 + 3][am0] = pa0.w;
            As[nxt][ak4 * 4 + 0][am1] = pa1.x; As[nxt][ak4 * 4 + 1][am1] = pa1.y;
            As[nxt][ak4 * 4 + 2][am1] = pa1.z; As[nxt][ak4 * 4 + 3][am1] = pa1.w;
            Bs[nxt][bk4 * 4 + 0][bn0] = pb.x;  Bs[nxt][bk4 * 4 + 1][bn0] = pb.y;
            Bs[nxt][bk4 * 4 + 2][bn0] = pb.z;  Bs[nxt][bk4 * 4 + 3][bn0] = pb.w;
            __syncthreads();
        }
    }

    #pragma unroll
    for (int i2 = 0; i2 < 4; i2++) {
        #pragma unroll
        for (int p = 0; p < 2; p++) {
            int gm = bm + ty * 8 + i2 * 2 + p;
            if (gm >= M) continue;
            #pragma unroll
            for (int j = 0; j < 4; j++) {
                float lo, hi;
                upk2(lo, hi, acc[i2][j]);
                float v = p ? hi : lo;
                int gn = bn + tx * 4 + j;
                if (gn >= N) continue;
                if (bias) v += bias[gn];
                if (relu) v = fmaxf(v, 0.f);
                C[(size_t)gm * ldc + gn] = v;
            }
        }
    }
}

__global__ __launch_bounds__(256)
void gemm_generic(const float* __restrict__ Aext, int Asel,
                  const float* __restrict__ B,
                  const float* __restrict__ bias,
                  float* __restrict__ Cext, int Csel,
                  int M, int N, int K, int lda, int ldc, int relu)
{
    const float* A = (Asel == 1) ? g_X0 : (Asel == 2) ? g_X1 : Aext;
    float* C = (Csel == 1) ? g_X0 : (Csel == 2) ? g_X1 : Cext;
    gemm_core(A, lda, B, bias, C, ldc, M, N, K, relu,
              blockIdx.x * 128, blockIdx.y * 64);
}

// ---------------- HMMA layer GEMM: U = X @ W^T (bf16-split-3) ---------------
// grid (79, 17), 256 threads (8 warps: 4m x 2n). Block tile 128x64, K=128 in
// 4 chunks of 32. mma.sync m16n8k16 bf16, fp32 acc; ldmatrix from padded smem.
__global__ __launch_bounds__(256)
void hmma_layer(const float* __restrict__ res_b)
{
    __shared__ __nv_bfloat16 sAh[128][40];
    __shared__ __nv_bfloat16 sAl[128][40];
    __shared__ __nv_bfloat16 sBh[64][40];
    __shared__ __nv_bfloat16 sBl[64][40];

    const int tid = threadIdx.x;
    const int lane = tid & 31, wid = tid >> 5;
    const int wm = wid >> 1, wn = wid & 1;
    const int bm = blockIdx.x * 128;
    const int tn = blockIdx.y;
    const size_t bnrow = (size_t)tn * 64;

    float acc[2][4][4];
    #pragma unroll
    for (int i = 0; i < 2; i++)
        #pragma unroll
        for (int j = 0; j < 4; j++)
            #pragma unroll
            for (int q = 0; q < 4; q++) acc[i][j][q] = 0.f;

    const uint32_t aHiB = smem_u32(&sAh[0][0]);
    const uint32_t aLoB = smem_u32(&sAl[0][0]);
    const uint32_t bHiB = smem_u32(&sBh[0][0]);
    const uint32_t bLoB = smem_u32(&sBl[0][0]);

    // ldmatrix per-lane offsets (in elements), computed once
    const int aRow = wm * 32 + (lane & 15);
    const int aColOff = (lane >> 4) * 8;
    const int bRow = wn * 32 + (lane & 7) + ((lane >> 4) & 1) * 8;
    const int bColOff = ((lane >> 3) & 1) * 8;

    for (int kc = 0; kc < 128; kc += 32) {
        // stage A (128x32) and B (64x32), hi+lo, uint4 per 8 bf16
        #pragma unroll
        for (int i = 0; i < 2; i++) {
            int idx = tid + i * 256;
            int r = idx >> 2, q = idx & 3;
            size_t src = (size_t)(bm + r) * 128 + kc + q * 8;
            *(uint4*)&sAh[r][q * 8] = *(const uint4*)(g_Xhi + src);
            *(uint4*)&sAl[r][q * 8] = *(const uint4*)(g_Xlo + src);
        }
        {
            int r = tid >> 2, q = tid & 3;
            size_t src = (bnrow + r) * 128 + kc + q * 8;
            *(uint4*)&sBh[r][q * 8] = *(const uint4*)(g_Whi + src);
            *(uint4*)&sBl[r][q * 8] = *(const uint4*)(g_Wlo + src);
        }
        __syncthreads();

        #pragma unroll
        for (int ks = 0; ks < 2; ks++) {
            int kk = ks * 16;
            uint32_t ah[2][4], al[2][4];
            #pragma unroll
            for (int mi = 0; mi < 2; mi++) {
                uint32_t off = (uint32_t)(((aRow + mi * 16) * 40 + kk + aColOff) * 2);
                LDSM_X4(ah[mi], aHiB + off);
                LDSM_X4(al[mi], aLoB + off);
            }
            uint32_t bh0[4], bl0[4], bh1[4], bl1[4];
            {
                uint32_t off0 = (uint32_t)((bRow * 40 + kk + bColOff) * 2);
                uint32_t off1 = (uint32_t)(((bRow + 16) * 40 + kk + bColOff) * 2);
                LDSM_X4(bh0, bHiB + off0);
                LDSM_X4(bl0, bLoB + off0);
                LDSM_X4(bh1, bHiB + off1);
                LDSM_X4(bl1, bLoB + off1);
            }
            #pragma unroll
            for (int mi = 0; mi < 2; mi++) {
                MMA_BF16(acc[mi][0], ah[mi], bh0[0], bh0[1]);
                MMA_BF16(acc[mi][0], ah[mi], bl0[0], bl0[1]);
                MMA_BF16(acc[mi][0], al[mi], bh0[0], bh0[1]);
                MMA_BF16(acc[mi][1], ah[mi], bh0[2], bh0[3]);
                MMA_BF16(acc[mi][1], ah[mi], bl0[2], bl0[3]);
                MMA_BF16(acc[mi][1], al[mi], bh0[2], bh0[3]);
                MMA_BF16(acc[mi][2], ah[mi], bh1[0], bh1[1]);
                MMA_BF16(acc[mi][2], ah[mi], bl1[0], bl1[1]);
                MMA_BF16(acc[mi][2], al[mi], bh1[0], bh1[1]);
                MMA_BF16(acc[mi][3], ah[mi], bh1[2], bh1[3]);
                MMA_BF16(acc[mi][3], ah[mi], bl1[2], bl1[3]);
                MMA_BF16(acc[mi][3], al[mi], bh1[2], bh1[3]);
            }
        }
        __syncthreads();
    }

    // epilogue: c0,c1 -> (row g, cols tig*2, +1); c2,c3 -> (row g+8, same cols)
    const int g = lane >> 2, tig = lane & 3;
    const bool isres = (tn >= 8 && tn < 16);
    #pragma unroll
    for (int mi = 0; mi < 2; mi++) {
        #pragma unroll
        for (int ni = 0; ni < 4; ni++) {
            int gn = tn * 64 + wn * 32 + ni * 8 + tig * 2;
            if (gn >= UC) continue;
            float bx = 0.f, by = 0.f;
            if (isres) { bx = res_b[gn - 512]; by = res_b[gn - 511]; }
            int gm0 = bm + wm * 32 + mi * 16 + g;
            if (gm0 < NNODES) {
                float2 o = make_float2(acc[mi][ni][0] + bx, acc[mi][ni][1] + by);
                *(float2*)(g_U + (size_t)gm0 * UC + gn) = o;
            }
            int gm1 = gm0 + 8;
            if (gm1 < NNODES) {
                float2 o = make_float2(acc[mi][ni][2] + bx, acc[mi][ni][3] + by);
                *(float2*)(g_U + (size_t)gm1 * UC + gn) = o;
            }
        }
    }
}

// ---------------- GAT aggregation + fused GraphCON epilogue ----------------
__global__ __launch_bounds__(128)
void node_kernel(const float* __restrict__ gat_b, int out_sel, int zero_dc)
{
    float* Xnew = (out_sel == 1) ? g_X0 : g_X1;
    const int d = blockIdx.x, t = threadIdx.x;
    const int h = t >> 5;

    __shared__ float s_adv[4];
    __shared__ float s_ls [4];
    __shared__ float sw[128];
    __shared__ int   si[32];

    const float* ud = g_U + (size_t)d * UC;
    if (t < 4) {
        float adv = ud[1028 + t];
        s_adv[t] = adv;
        s_ls[t]  = lrelu(ud[1024 + t] + adv);
    }
    if (zero_dc && t == 0) { g_deg[d] = 0; g_cur[d] = 0; }
    __syncthreads();

    const int e0 = g_off[d], e1 = g_off[d + 1];

    float ssum = 1.f;
    float4 acc = ((const float4*)ud)[t];

    const int jj = t >> 2, hh = t & 3;
    const float adv_h = s_adv[hh];
    const float ls_h  = s_ls[hh];

    for (int base = e0; base < e1; base += 32) {
        int cnt = min(32, e1 - base);
        if (jj < cnt) {
            int s = g_csr[base + jj];
            if (hh == 0) si[jj] = s;
            float as = g_U[(size_t)s * UC + 1024 + hh];
            sw[jj * 4 + hh] = __expf(lrelu(as + adv_h) - ls_h);
        }
        __syncthreads();

        int j = 0;
        for (; j + 4 <= cnt; j += 4) {
            int s0 = si[j], s1 = si[j + 1], s2 = si[j + 2], s3 = si[j + 3];
            float w0 = sw[j * 4 + h],      w1 = sw[j * 4 + 4 + h];
            float w2 = sw[j * 4 + 8 + h],  w3 = sw[j * 4 + 12 + h];
            float4 v0 = ((const float4*)(g_U + (size_t)s0 * UC))[t];
            float4 v1 = ((const float4*)(g_U + (size_t)s1 * UC))[t];
            float4 v2 = ((const float4*)(g_U + (size_t)s2 * UC))[t];
            float4 v3 = ((const float4*)(g_U + (size_t)s3 * UC))[t];
            acc.x = fmaf(w0, v0.x, acc.x); acc.y = fmaf(w0, v0.y, acc.y);
            acc.z = fmaf(w0, v0.z, acc.z); acc.w = fmaf(w0, v0.w, acc.w);
            acc.x = fmaf(w1, v1.x, acc.x); acc.y = fmaf(w1, v1.y, acc.y);
            acc.z = fmaf(w1, v1.z, acc.z); acc.w = fmaf(w1, v1.w, acc.w);
            acc.x = fmaf(w2, v2.x, acc.x); acc.y = fmaf(w2, v2.y, acc.y);
            acc.z = fmaf(w2, v2.z, acc.z); acc.w = fmaf(w2, v2.w, acc.w);
            acc.x = fmaf(w3, v3.x, acc.x); acc.y = fmaf(w3, v3.y, acc.y);
            acc.z = fmaf(w3, v3.z, acc.z); acc.w = fmaf(w3, v3.w, acc.w);
            ssum += (w0 + w1) + (w2 + w3);
        }
        for (; j < cnt; j++) {
            int s0 = si[j];
            float w0 = sw[j * 4 + h];
            float4 v0 = ((const float4*)(g_U + (size_t)s0 * UC))[t];
            acc.x = fmaf(w0, v0.x, acc.x); acc.y = fmaf(w0, v0.y, acc.y);
            acc.z = fmaf(w0, v0.z, acc.z); acc.w = fmaf(w0, v0.w, acc.w);
            ssum += w0;
        }
        __syncthreads();
    }

    float rcp = 1.f / ssum;
    float4 gb = ((const float4*)gat_b)[t];
    float4 rs = ((const float4*)(ud + 512))[t];
    float z = 0.25f * (eluf(fmaf(acc.x, rcp, gb.x + rs.x)) +
                       eluf(fmaf(acc.y, rcp, gb.y + rs.y)) +
                       eluf(fmaf(acc.z, rcp, gb.z + rs.z)) +
                       eluf(fmaf(acc.w, rcp, gb.w + rs.w)));
    Xnew[(size_t)d * NHID + t] = z;
}

// ---------------- host ------------------------------------------------------
extern "C" void kernel_launch(void* const* d_in, const int* in_sizes, int n_in,
                              void* d_out, int out_size)
{
    const float* x       = (const float*)d_in[0];
    const void*  ei      = d_in[1];
    const float* enc_w   = (const float*)d_in[2];
    const float* enc_b   = (const float*)d_in[3];
    const float* res_w   = (const float*)d_in[4];
    const float* res_b   = (const float*)d_in[5];
    const float* gat_w   = (const float*)d_in[6];
    const float* att_src = (const float*)d_in[7];
    const float* att_dst = (const float*)d_in[8];
    const float* gat_b   = (const float*)d_in[9];
    const float* dec_w   = (const float*)d_in[10];
    const float* dec_b   = (const float*)d_in[11];
    int E = in_sizes[1] / 2;

    cudaStream_t s2;
    cudaStreamCreateWithFlags(&s2, cudaStreamNonBlocking);
    cudaEvent_t evA, evB;
    cudaEventCreateWithFlags(&evA, cudaEventDisableTiming);
    cudaEventCreateWithFlags(&evB, cudaEventDisableTiming);

    // folds + dtype sniff; weight split
    init_kernel<<<9, 128>>>(ei, gat_w, att_src, att_dst);
    conv_w_kernel<<<NBPAD, 128>>>(gat_w, res_w);

    // fork: CSR build on side stream
    cudaEventRecord(evA, 0);
    cudaStreamWaitEvent(s2, evA, 0);
    count_kernel<<<(E + 255) / 256, 256, 0, s2>>>(ei, E);
    scan_kernel<<<1, 1024, 0, s2>>>(NNODES);
    scatter_kernel<<<(E + 255) / 256, 256, 0, s2>>>(ei, E);
    cudaEventRecord(evB, s2);

    // encoder: X0 = relu(x @ enc_w^T + enc_b)
    gemm_generic<<<dim3(79, 2), 256>>>(x, 0, enc_w, enc_b, nullptr, 1,
                                       NNODES, 128, 256, 256, 128, 1);

    // layer 0
    conv_x_kernel<<<NPAD * 128 / 256, 256>>>(1);
    hmma_layer<<<dim3(79, 17), 256>>>(res_b);
    cudaStreamWaitEvent(0, evB, 0);
    node_kernel<<<NNODES, 128>>>(gat_b, 2, 1);

    // layer 1
    conv_x_kernel<<<NPAD * 128 / 256, 256>>>(2);
    hmma_layer<<<dim3(79, 17), 256>>>(res_b);
    node_kernel<<<NNODES, 128>>>(gat_b, 1, 0);

    // decoder: out = X0 @ dec_w^T + dec_b
    gemm_generic<<<dim3(79, 1), 256>>>(nullptr, 1, dec_w, dec_b,
                                       (float*)d_out, 0,
                                       NNODES, 40, 128, 128, 40, 0);
}

// round 12
// speedup vs baseline: 1.4155x; 1.0351x over previous
#include <cuda_runtime.h>
#include <cuda_bf16.h>
#include <math.h>
#include <stdint.h>

#define NNODES 10000
#define NPAD   10112     // 79*128
#define NHID   128
#define UC     1032      // U row: xh(512) | res(512) | a_src(4) | a_dst(4)
#define NBPAD  1088      // 17*64
#define EMAX   160000

// ---------------- scratch (device globals; no allocation allowed) ----------
__device__ float g_X0[NNODES * NHID];
__device__ float g_X1[NNODES * NHID];
__device__ float g_U [NNODES * UC];
__device__ float g_fold[8 * 128];
__device__ __nv_bfloat16 g_Xhi [NPAD * 128];   // current-layer activations (split)
__device__ __nv_bfloat16 g_Xlo [NPAD * 128];
__device__ __nv_bfloat16 g_XIhi[NPAD * 256];   // encoder input x (split)
__device__ __nv_bfloat16 g_XIlo[NPAD * 256];
__device__ __nv_bfloat16 g_Whi[NBPAD * 128];   // layer weights (split)
__device__ __nv_bfloat16 g_Wlo[NBPAD * 128];
__device__ __nv_bfloat16 g_Ehi[128 * 256];     // enc_w (split)
__device__ __nv_bfloat16 g_Elo[128 * 256];
__device__ int   g_deg[NNODES];
__device__ int   g_cur[NNODES];
__device__ int   g_off[NNODES + 1];
__device__ int   g_csr[EMAX];
__device__ int   g_is64;

// ---------------- helpers ---------------------------------------------------
__device__ __forceinline__ float lrelu(float x) { return x > 0.f ? x : 0.2f * x; }
__device__ __forceinline__ float eluf (float x) { return x > 0.f ? x : (__expf(x) - 1.f); }

__device__ __forceinline__ unsigned long long pk2(float lo, float hi) {
    unsigned long long r;
    asm("mov.b64 %0, {%1, %2};" : "=l"(r) : "f"(lo), "f"(hi));
    return r;
}
__device__ __forceinline__ void fma2(unsigned long long& d,
                                     unsigned long long a, unsigned long long b) {
    asm("fma.rn.f32x2 %0, %1, %2, %3;" : "=l"(d) : "l"(a), "l"(b), "l"(d));
}
__device__ __forceinline__ void upk2(float& lo, float& hi, unsigned long long v) {
    asm("mov.b64 {%0, %1}, %2;" : "=f"(lo), "=f"(hi) : "l"(v));
}

__device__ __forceinline__ int edge_at(const void* ei, int idx, int is64) {
    if (is64) return (int)((const long long*)ei)[idx];
    return ((const int*)ei)[idx];
}

__device__ __forceinline__ uint32_t smem_u32(const void* p) {
    uint32_t a;
    asm("{ .reg .u64 t; cvta.to.shared.u64 t, %1; cvt.u32.u64 %0, t; }"
        : "=r"(a) : "l"(p));
    return a;
}

#define LDSM_X4(r, addr)                                                        \
    asm volatile("ldmatrix.sync.aligned.m8n8.x4.shared.b16 {%0,%1,%2,%3}, [%4];" \
        : "=r"((r)[0]), "=r"((r)[1]), "=r"((r)[2]), "=r"((r)[3]) : "r"(addr))

#define MMA_BF16(c, a, b0_, b1_)                                                \
    asm volatile("mma.sync.aligned.m16n8k16.row.col.f32.bf16.bf16.f32 "         \
        "{%0,%1,%2,%3}, {%4,%5,%6,%7}, {%8,%9}, {%0,%1,%2,%3};"                 \
        : "+f"((c)[0]), "+f"((c)[1]), "+f"((c)[2]), "+f"((c)[3])                \
        : "r"((a)[0]), "r"((a)[1]), "r"((a)[2]), "r"((a)[3]), "r"(b0_), "r"(b1_))

__device__ __forceinline__ void split_write(__nv_bfloat16* hi, __nv_bfloat16* lo,
                                            size_t idx, float v) {
    __nv_bfloat16 h = __float2bfloat16(v);
    hi[idx] = h;
    lo[idx] = __float2bfloat16(v - __bfloat162float(h));
}

// ---------------- init: fold rows (blocks 0..7) + dtype sniff (block 8) -----
__global__ __launch_bounds__(128)
void init_kernel(const void* ei,
                 const float* __restrict__ gat_w,
                 const float* __restrict__ att_src,
                 const float* __restrict__ att_dst)
{
    int b = blockIdx.x, t = threadIdx.x;
    if (b < 8) {
        int h = b & 3;
        const float* att = (b < 4) ? att_src : att_dst;
        float s = 0.f;
        for (int k = 0; k < 128; k++)
            s = fmaf(att[h * 128 + k], gat_w[(size_t)(h * 128 + k) * 128 + t], s);
        g_fold[b * 128 + t] = s;
    } else {
        __shared__ int acc[128];
        const unsigned* w = (const unsigned*)ei;
        unsigned o = 0;
        #pragma unroll
        for (int j = 0; j < 16; j++) o |= w[(t + j * 128) * 2 + 1];
        acc[t] = (int)(o != 0);
        __syncthreads();
        for (int s = 64; s > 0; s >>= 1) {
            if (t < s) acc[t] |= acc[t + s];
            __syncthreads();
        }
        if (t == 0) g_is64 = acc[0] ? 0 : 1;
    }
}

// ---------------- weight conversions -----------------------------------------
__global__ __launch_bounds__(128)
void conv_w_kernel(const float* __restrict__ gat_w,
                   const float* __restrict__ res_w)
{
    int r = blockIdx.x, t = threadIdx.x;
    float v = 0.f;
    if (r < 512)       v = gat_w[(size_t)r * 128 + t];
    else if (r < 1024) v = res_w[(size_t)(r - 512) * 128 + t];
    else if (r < 1032) v = g_fold[(r - 1024) * 128 + t];
    split_write(g_Whi, g_Wlo, (size_t)r * 128 + t, v);
}

__global__ __launch_bounds__(256)
void conv_ew_kernel(const float* __restrict__ enc_w)
{
    int r = blockIdx.x, t = threadIdx.x;          // 128 blocks x 256 threads
    split_write(g_Ehi, g_Elo, (size_t)r * 256 + t, enc_w[(size_t)r * 256 + t]);
}

__global__ __launch_bounds__(256)
void conv_xin_kernel(const float* __restrict__ x)
{
    int idx = blockIdx.x * 256 + threadIdx.x;     // < NPAD*256
    float v = (idx < NNODES * 256) ? x[idx] : 0.f;
    split_write(g_XIhi, g_XIlo, idx, v);
}

// ---------------- CSR build -------------------------------------------------
__global__ void count_kernel(const void* __restrict__ ei, int E) {
    int e = blockIdx.x * blockDim.x + threadIdx.x;
    if (e < E) atomicAdd(&g_deg[edge_at(ei, E + e, g_is64)], 1);
}

__global__ void scan_kernel(int n) {
    __shared__ int wsum[32];
    int t = threadIdx.x, lane = t & 31, w = t >> 5;
    const int chunk = 10;
    int base_i = t * chunk;
    int s = 0;
    #pragma unroll
    for (int i = 0; i < chunk; i++) {
        int idx = base_i + i;
        if (idx < n) s += g_deg[idx];
    }
    int v = s;
    #pragma unroll
    for (int o = 1; o < 32; o <<= 1) {
        int u = __shfl_up_sync(0xffffffffu, v, o);
        if (lane >= o) v += u;
    }
    if (lane == 31) wsum[w] = v;
    __syncthreads();
    if (w == 0) {
        int x = wsum[lane];
        #pragma unroll
        for (int o = 1; o < 32; o <<= 1) {
            int u = __shfl_up_sync(0xffffffffu, x, o);
            if (lane >= o) x += u;
        }
        wsum[lane] = x;
    }
    __syncthreads();
    int run = (w ? wsum[w - 1] : 0) + v - s;
    #pragma unroll
    for (int i = 0; i < chunk; i++) {
        int idx = base_i + i;
        if (idx < n) { g_off[idx] = run; run += g_deg[idx]; }
    }
    if (t == 1023) g_off[n] = run;
}

__global__ void scatter_kernel(const void* __restrict__ ei, int E) {
    int e = blockIdx.x * blockDim.x + threadIdx.x;
    if (e < E) {
        int is64 = g_is64;
        int d = edge_at(ei, E + e, is64);
        int p = g_off[d] + atomicAdd(&g_cur[d], 1);
        g_csr[p] = edge_at(ei, e, is64);
    }
}

// ---------------- SIMT GEMM (decoder) ----------------------------------------
__global__ __launch_bounds__(256)
void gemm_dec(const float* __restrict__ B,
              const float* __restrict__ bias,
              float* __restrict__ C,
              int M, int N, int K)
{
    const float* A = g_X0;
    __shared__ float As[2][16][132];
    __shared__ float Bs[2][16][68];

    const int tid = threadIdx.x;
    const int tx = tid & 15, ty = tid >> 4;
    const int am0 = tid >> 2, am1 = 64 + (tid >> 2), ak4 = tid & 3;
    const int bn0 = tid >> 2, bk4 = tid & 3;
    const int bm = blockIdx.x * 128, bn = 0;

    const int gn_row = bn + bn0;
    const float* brow = B + (size_t)gn_row * K;

    float4 pa0, pa1, pb;
    const int nt = K >> 4;

    {
        int gm0 = bm + am0, gm1 = bm + am1;
        pa0 = (gm0 < M) ? *(const float4*)(A + (size_t)gm0 * K + ak4 * 4) : make_float4(0, 0, 0, 0);
        pa1 = (gm1 < M) ? *(const float4*)(A + (size_t)gm1 * K + ak4 * 4) : make_float4(0, 0, 0, 0);
        pb  = (gn_row < N) ? *(const float4*)(brow + bk4 * 4) : make_float4(0, 0, 0, 0);
        As[0][ak4 * 4 + 0][am0] = pa0.x; As[0][ak4 * 4 + 1][am0] = pa0.y;
        As[0][ak4 * 4 + 2][am0] = pa0.z; As[0][ak4 * 4 + 3][am0] = pa0.w;
        As[0][ak4 * 4 + 0][am1] = pa1.x; As[0][ak4 * 4 + 1][am1] = pa1.y;
        As[0][ak4 * 4 + 2][am1] = pa1.z; As[0][ak4 * 4 + 3][am1] = pa1.w;
        Bs[0][bk4 * 4 + 0][bn0] = pb.x;  Bs[0][bk4 * 4 + 1][bn0] = pb.y;
        Bs[0][bk4 * 4 + 2][bn0] = pb.z;  Bs[0][bk4 * 4 + 3][bn0] = pb.w;
    }
    __syncthreads();

    unsigned long long acc[4][4];
    const unsigned long long zz = pk2(0.f, 0.f);
    #pragma unroll
    for (int i = 0; i < 4; i++)
        #pragma unroll
        for (int j = 0; j < 4; j++) acc[i][j] = zz;

    for (int t = 0; t < nt; t++) {
        int cur = t & 1;
        if (t + 1 < nt) {
            int kt = (t + 1) << 4;
            int gm0 = bm + am0, gm1 = bm + am1;
            pa0 = (gm0 < M) ? *(const float4*)(A + (size_t)gm0 * K + kt + ak4 * 4) : make_float4(0, 0, 0, 0);
            pa1 = (gm1 < M) ? *(const float4*)(A + (size_t)gm1 * K + kt + ak4 * 4) : make_float4(0, 0, 0, 0);
            pb  = (gn_row < N) ? *(const float4*)(brow + kt + bk4 * 4) : make_float4(0, 0, 0, 0);
        }
        #pragma unroll
        for (int k = 0; k < 16; k++) {
            ulonglong2 ap0 = *(const ulonglong2*)&As[cur][k][ty * 8];
            ulonglong2 ap1 = *(const ulonglong2*)&As[cur][k][ty * 8 + 4];
            float4 bv = *(const float4*)&Bs[cur][k][tx * 4];
            unsigned long long ad[4] = {ap0.x, ap0.y, ap1.x, ap1.y};
            unsigned long long bd[4] = {pk2(bv.x, bv.x), pk2(bv.y, bv.y),
                                        pk2(bv.z, bv.z), pk2(bv.w, bv.w)};
            #pragma unroll
            for (int i = 0; i < 4; i++) {
                fma2(acc[i][0], ad[i], bd[0]);
                fma2(acc[i][1], ad[i], bd[1]);
                fma2(acc[i][2], ad[i], bd[2]);
                fma2(acc[i][3], ad[i], bd[3]);
            }
        }
        if (t + 1 < nt) {
            int nxt = cur ^ 1;
            As[nxt][ak4 * 4 + 0][am0] = pa0.x; As[nxt][ak4 * 4 + 1][am0] = pa0.y;
            As[nxt][ak4 * 4 + 2][am0] = pa0.z; As[nxt][ak4 * 4 + 3][am0] = pa0.w;
            As[nxt][ak4 * 4 + 0][am1] = pa1.x; As[nxt][ak4 * 4 + 1][am1] = pa1.y;
            As[nxt][ak4 * 4 + 2][am1] = pa1.z; As[nxt][ak4 * 4 + 3][am1] = pa1.w;
            Bs[nxt][bk4 * 4 + 0][bn0] = pb.x;  Bs[nxt][bk4 * 4 + 1][bn0] = pb.y;
            Bs[nxt][bk4 * 4 + 2][bn0] = pb.z;  Bs[nxt][bk4 * 4 + 3][bn0] = pb.w;
            __syncthreads();
        }
    }

    #pragma unroll
    for (int i2 = 0; i2 < 4; i2++) {
        #pragma unroll
        for (int p = 0; p < 2; p++) {
            int gm = bm + ty * 8 + i2 * 2 + p;
            if (gm >= M) continue;
            #pragma unroll
            for (int j = 0; j < 4; j++) {
                float lo, hi;
                upk2(lo, hi, acc[i2][j]);
                float v = p ? hi : lo;
                int gn = bn + tx * 4 + j;
                if (gn >= N) continue;
                v += bias[gn];
                C[(size_t)gm * N + gn] = v;
            }
        }
    }
}

// ---------------- HMMA GEMM (bf16-split-3) -----------------------------------
// EPI 0: layer  — A=g_Xhi/g_Xlo (lda 128), B=g_Whi/g_Wlo, out g_U (+res_b cols)
// EPI 1: encoder— A=g_XIhi/g_XIlo (lda 256), B=g_Ehi/g_Elo, out X0 relu + split
// grid (79, ntiles), 256 threads (8 warps: 4m x 2n). Block tile 128x64.
template<int EPI>
__global__ __launch_bounds__(256)
void hmma_gemm(const float* __restrict__ bias)
{
    __shared__ __nv_bfloat16 sAh[128][40];
    __shared__ __nv_bfloat16 sAl[128][40];
    __shared__ __nv_bfloat16 sBh[64][40];
    __shared__ __nv_bfloat16 sBl[64][40];

    const int tid = threadIdx.x;
    const int lane = tid & 31, wid = tid >> 5;
    const int wm = wid >> 1, wn = wid & 1;
    const int bm = blockIdx.x * 128;
    const int tn = blockIdx.y;

    const int K   = (EPI == 1) ? 256 : 128;
    const __nv_bfloat16* Ahi = (EPI == 1) ? g_XIhi : g_Xhi;
    const __nv_bfloat16* Alo = (EPI == 1) ? g_XIlo : g_Xlo;
    const __nv_bfloat16* Bhi = (EPI == 1) ? g_Ehi : g_Whi;
    const __nv_bfloat16* Blo = (EPI == 1) ? g_Elo : g_Wlo;
    const size_t bnrow = (size_t)tn * 64;

    float acc[2][4][4];
    #pragma unroll
    for (int i = 0; i < 2; i++)
        #pragma unroll
        for (int j = 0; j < 4; j++)
            #pragma unroll
            for (int q = 0; q < 4; q++) acc[i][j][q] = 0.f;

    const uint32_t aHiB = smem_u32(&sAh[0][0]);
    const uint32_t aLoB = smem_u32(&sAl[0][0]);
    const uint32_t bHiB = smem_u32(&sBh[0][0]);
    const uint32_t bLoB = smem_u32(&sBl[0][0]);

    const int aRow = wm * 32 + (lane & 15);
    const int aColOff = (lane >> 4) * 8;
    const int bRow = wn * 32 + (lane & 7) + ((lane >> 4) & 1) * 8;
    const int bColOff = ((lane >> 3) & 1) * 8;

    for (int kc = 0; kc < K; kc += 32) {
        #pragma unroll
        for (int i = 0; i < 2; i++) {
            int idx = tid + i * 256;
            int r = idx >> 2, q = idx & 3;
            size_t src = (size_t)(bm + r) * K + kc + q * 8;
            *(uint4*)&sAh[r][q * 8] = *(const uint4*)(Ahi + src);
            *(uint4*)&sAl[r][q * 8] = *(const uint4*)(Alo + src);
        }
        {
            int r = tid >> 2, q = tid & 3;
            size_t src = (bnrow + r) * K + kc + q * 8;
            *(uint4*)&sBh[r][q * 8] = *(const uint4*)(Bhi + src);
            *(uint4*)&sBl[r][q * 8] = *(const uint4*)(Blo + src);
        }
        __syncthreads();

        #pragma unroll
        for (int ks = 0; ks < 2; ks++) {
            int kk = ks * 16;
            uint32_t ah[2][4], al[2][4];
            #pragma unroll
            for (int mi = 0; mi < 2; mi++) {
                uint32_t off = (uint32_t)(((aRow + mi * 16) * 40 + kk + aColOff) * 2);
                LDSM_X4(ah[mi], aHiB + off);
                LDSM_X4(al[mi], aLoB + off);
            }
            uint32_t bh0[4], bl0[4], bh1[4], bl1[4];
            {
                uint32_t off0 = (uint32_t)((bRow * 40 + kk + bColOff) * 2);
                uint32_t off1 = (uint32_t)(((bRow + 16) * 40 + kk + bColOff) * 2);
                LDSM_X4(bh0, bHiB + off0);
                LDSM_X4(bl0, bLoB + off0);
                LDSM_X4(bh1, bHiB + off1);
                LDSM_X4(bl1, bLoB + off1);
            }
            #pragma unroll
            for (int mi = 0; mi < 2; mi++) {
                MMA_BF16(acc[mi][0], ah[mi], bh0[0], bh0[1]);
                MMA_BF16(acc[mi][0], ah[mi], bl0[0], bl0[1]);
                MMA_BF16(acc[mi][0], al[mi], bh0[0], bh0[1]);
                MMA_BF16(acc[mi][1], ah[mi], bh0[2], bh0[3]);
                MMA_BF16(acc[mi][1], ah[mi], bl0[2], bl0[3]);
                MMA_BF16(acc[mi][1], al[mi], bh0[2], bh0[3]);
                MMA_BF16(acc[mi][2], ah[mi], bh1[0], bh1[1]);
                MMA_BF16(acc[mi][2], ah[mi], bl1[0], bl1[1]);
                MMA_BF16(acc[mi][2], al[mi], bh1[0], bh1[1]);
                MMA_BF16(acc[mi][3], ah[mi], bh1[2], bh1[3]);
                MMA_BF16(acc[mi][3], ah[mi], bl1[2], bl1[3]);
                MMA_BF16(acc[mi][3], al[mi], bh1[2], bh1[3]);
            }
        }
        __syncthreads();
    }

    const int g = lane >> 2, tig = lane & 3;
    #pragma unroll
    for (int mi = 0; mi < 2; mi++) {
        #pragma unroll
        for (int ni = 0; ni < 4; ni++) {
            int gn = tn * 64 + wn * 32 + ni * 8 + tig * 2;
            int gm0 = bm + wm * 32 + mi * 16 + g;
            if (EPI == 0) {
                if (gn >= UC) continue;
                const bool isres = (tn >= 8 && tn < 16);
                float bx = 0.f, by = 0.f;
                if (isres) { bx = bias[gn - 512]; by = bias[gn - 511]; }
                if (gm0 < NNODES) {
                    float2 o = make_float2(acc[mi][ni][0] + bx, acc[mi][ni][1] + by);
                    *(float2*)(g_U + (size_t)gm0 * UC + gn) = o;
                }
                int gm1 = gm0 + 8;
                if (gm1 < NNODES) {
                    float2 o = make_float2(acc[mi][ni][2] + bx, acc[mi][ni][3] + by);
                    *(float2*)(g_U + (size_t)gm1 * UC + gn) = o;
                }
            } else {
                float bx = bias[gn], by = bias[gn + 1];
                if (gm0 < NNODES) {
                    float vx = fmaxf(acc[mi][ni][0] + bx, 0.f);
                    float vy = fmaxf(acc[mi][ni][1] + by, 0.f);
                    size_t o = (size_t)gm0 * 128 + gn;
                    *(float2*)(g_X0 + o) = make_float2(vx, vy);
                    split_write(g_Xhi, g_Xlo, o, vx);
                    split_write(g_Xhi, g_Xlo, o + 1, vy);
                }
                int gm1 = gm0 + 8;
                if (gm1 < NNODES) {
                    float vx = fmaxf(acc[mi][ni][2] + bx, 0.f);
                    float vy = fmaxf(acc[mi][ni][3] + by, 0.f);
                    size_t o = (size_t)gm1 * 128 + gn;
                    *(float2*)(g_X0 + o) = make_float2(vx, vy);
                    split_write(g_Xhi, g_Xlo, o, vx);
                    split_write(g_Xhi, g_Xlo, o + 1, vy);
                }
            }
        }
    }
}

// ---------------- GAT aggregation + fused GraphCON epilogue ----------------
__global__ __launch_bounds__(128)
void node_kernel(const float* __restrict__ gat_b, int out_sel,
                 int zero_dc, int write_split)
{
    float* Xnew = (out_sel == 1) ? g_X0 : g_X1;
    const int d = blockIdx.x, t = threadIdx.x;
    const int h = t >> 5;

    __shared__ float s_adv[4];
    __shared__ float s_ls [4];
    __shared__ float sw[128];
    __shared__ int   si[32];

    const float* ud = g_U + (size_t)d * UC;
    if (t < 4) {
        float adv = ud[1028 + t];
        s_adv[t] = adv;
        s_ls[t]  = lrelu(ud[1024 + t] + adv);
    }
    if (zero_dc && t == 0) { g_deg[d] = 0; g_cur[d] = 0; }
    __syncthreads();

    const int e0 = g_off[d], e1 = g_off[d + 1];

    float ssum = 1.f;
    float4 acc = ((const float4*)ud)[t];

    const int jj = t >> 2, hh = t & 3;
    const float adv_h = s_adv[hh];
    const float ls_h  = s_ls[hh];

    for (int base = e0; base < e1; base += 32) {
        int cnt = min(32, e1 - base);
        if (jj < cnt) {
            int s = g_csr[base + jj];
            if (hh == 0) si[jj] = s;
            float as = g_U[(size_t)s * UC + 1024 + hh];
            sw[jj * 4 + hh] = __expf(lrelu(as + adv_h) - ls_h);
        }
        __syncthreads();

        int j = 0;
        for (; j + 4 <= cnt; j += 4) {
            int s0 = si[j], s1 = si[j + 1], s2 = si[j + 2], s3 = si[j + 3];
            float w0 = sw[j * 4 + h],      w1 = sw[j * 4 + 4 + h];
            float w2 = sw[j * 4 + 8 + h],  w3 = sw[j * 4 + 12 + h];
            float4 v0 = ((const float4*)(g_U + (size_t)s0 * UC))[t];
            float4 v1 = ((const float4*)(g_U + (size_t)s1 * UC))[t];
            float4 v2 = ((const float4*)(g_U + (size_t)s2 * UC))[t];
            float4 v3 = ((const float4*)(g_U + (size_t)s3 * UC))[t];
            acc.x = fmaf(w0, v0.x, acc.x); acc.y = fmaf(w0, v0.y, acc.y);
            acc.z = fmaf(w0, v0.z, acc.z); acc.w = fmaf(w0, v0.w, acc.w);
            acc.x = fmaf(w1, v1.x, acc.x); acc.y = fmaf(w1, v1.y, acc.y);
            acc.z = fmaf(w1, v1.z, acc.z); acc.w = fmaf(w1, v1.w, acc.w);
            acc.x = fmaf(w2, v2.x, acc.x); acc.y = fmaf(w2, v2.y, acc.y);
            acc.z = fmaf(w2, v2.z, acc.z); acc.w = fmaf(w2, v2.w, acc.w);
            acc.x = fmaf(w3, v3.x, acc.x); acc.y = fmaf(w3, v3.y, acc.y);
            acc.z = fmaf(w3, v3.z, acc.z); acc.w = fmaf(w3, v3.w, acc.w);
            ssum += (w0 + w1) + (w2 + w3);
        }
        for (; j < cnt; j++) {
            int s0 = si[j];
            float w0 = sw[j * 4 + h];
            float4 v0 = ((const float4*)(g_U + (size_t)s0 * UC))[t];
            acc.x = fmaf(w0, v0.x, acc.x); acc.y = fmaf(w0, v0.y, acc.y);
            acc.z = fmaf(w0, v0.z, acc.z); acc.w = fmaf(w0, v0.w, acc.w);
            ssum += w0;
        }
        __syncthreads();
    }

    float rcp = 1.f / ssum;
    float4 gb = ((const float4*)gat_b)[t];
    float4 rs = ((const float4*)(ud + 512))[t];
    float z = 0.25f * (eluf(fmaf(acc.x, rcp, gb.x + rs.x)) +
                       eluf(fmaf(acc.y, rcp, gb.y + rs.y)) +
                       eluf(fmaf(acc.z, rcp, gb.z + rs.z)) +
                       eluf(fmaf(acc.w, rcp, gb.w + rs.w)));
    size_t o = (size_t)d * NHID + t;
    Xnew[o] = z;
    if (write_split) split_write(g_Xhi, g_Xlo, o, z);
}

// ---------------- host ------------------------------------------------------
extern "C" void kernel_launch(void* const* d_in, const int* in_sizes, int n_in,
                              void* d_out, int out_size)
{
    const float* x       = (const float*)d_in[0];
    const void*  ei      = d_in[1];
    const float* enc_w   = (const float*)d_in[2];
    const float* enc_b   = (const float*)d_in[3];
    const float* res_w   = (const float*)d_in[4];
    const float* res_b   = (const float*)d_in[5];
    const float* gat_w   = (const float*)d_in[6];
    const float* att_src = (const float*)d_in[7];
    const float* att_dst = (const float*)d_in[8];
    const float* gat_b   = (const float*)d_in[9];
    const float* dec_w   = (const float*)d_in[10];
    const float* dec_b   = (const float*)d_in[11];
    int E = in_sizes[1] / 2;

    cudaStream_t s2;
    cudaStreamCreateWithFlags(&s2, cudaStreamNonBlocking);
    cudaEvent_t evA, evB;
    cudaEventCreateWithFlags(&evA, cudaEventDisableTiming);
    cudaEventCreateWithFlags(&evB, cudaEventDisableTiming);

    // folds + dtype sniff; weight + input conversions
    init_kernel<<<9, 128>>>(ei, gat_w, att_src, att_dst);

    // fork: CSR build on side stream (after sniff)
    cudaEventRecord(evA, 0);
    cudaStreamWaitEvent(s2, evA, 0);
    count_kernel<<<(E + 255) / 256, 256, 0, s2>>>(ei, E);
    scan_kernel<<<1, 1024, 0, s2>>>(NNODES);
    scatter_kernel<<<(E + 255) / 256, 256, 0, s2>>>(ei, E);
    cudaEventRecord(evB, s2);

    conv_w_kernel<<<NBPAD, 128>>>(gat_w, res_w);
    conv_ew_kernel<<<128, 256>>>(enc_w);
    conv_xin_kernel<<<NPAD * 256 / 256, 256>>>(x);

    // encoder (HMMA): X0 = relu(x @ enc_w^T + enc_b), also writes split
    hmma_gemm<1><<<dim3(79, 2), 256>>>(enc_b);

    // layer 0
    hmma_gemm<0><<<dim3(79, 17), 256>>>(res_b);
    cudaStreamWaitEvent(0, evB, 0);
    node_kernel<<<NNODES, 128>>>(gat_b, 2, 1, 1);   // writes X1 + split

    // layer 1
    hmma_gemm<0><<<dim3(79, 17), 256>>>(res_b);
    node_kernel<<<NNODES, 128>>>(gat_b, 1, 0, 0);   // writes X0

    // decoder: out = X0 @ dec_w^T + dec_b
    gemm_dec<<<79, 256>>>(dec_w, dec_b, (float*)d_out, NNODES, 40, 128);
}